// round 4
// baseline (speedup 1.0000x reference)
#include <cuda_runtime.h>

// Shapes (fixed by the problem)
#define N_  4096
#define M_  128
#define Q_  64
#define D_  128

#define BN  128       // n-rows per block
#define KC  32        // K staging chunk
#define NTH 128       // threads per block (16 tn x 8 tq)

// -0.5*inv_var*||a_n||^2 and -0.5*inv_var*||b_mq||^2
__device__ float g_ca[N_];
__device__ float g_cb[M_ * Q_];

// ---------------------------------------------------------------------------
// Prep: one warp per row, compute scaled squared norms.
// ---------------------------------------------------------------------------
__global__ __launch_bounds__(256) void kde_prep(const float* __restrict__ a,
                                                const float* __restrict__ b,
                                                const float* __restrict__ var) {
    int warp = (blockIdx.x * blockDim.x + threadIdx.x) >> 5;
    int lane = threadIdx.x & 31;
    const int R = N_ + M_ * Q_;
    if (warp >= R) return;
    const float* src = (warp < N_) ? (a + (size_t)warp * D_)
                                   : (b + (size_t)(warp - N_) * D_);
    float4 v = reinterpret_cast<const float4*>(src)[lane];   // 32 lanes * 4 = 128
    float s = v.x * v.x + v.y * v.y + v.z * v.z + v.w * v.w;
    #pragma unroll
    for (int o = 16; o; o >>= 1) s += __shfl_xor_sync(0xffffffffu, s, o);
    if (lane == 0) {
        float c = -0.5f * (1.0f / var[0]) * s;
        if (warp < N_) g_ca[warp] = c;
        else           g_cb[warp - N_] = c;
    }
}

// ---------------------------------------------------------------------------
// Main: block = (128 n-rows) x (one m cluster, all 64 q).
// dens[n][m] = sum_q exp(ca[n] + cb[m,q] + inv_var * dot(a_n, b_mq))
// Inner product via packed fma.rn.f32x2 (2 fp32 FMA per instruction).
// ---------------------------------------------------------------------------
union F4U { float4 f4; unsigned long long u[2]; float f[4]; };
union UPK { unsigned long long u; float f[2]; };

__global__ __launch_bounds__(NTH) void kde_main(const float* __restrict__ a,
                                                const float* __restrict__ b,
                                                const float* __restrict__ var,
                                                float* __restrict__ dens) {
    // transposed smem tiles: [k][n] / [k][q], padded to keep float4 alignment
    __shared__ float s_a[KC][BN + 4];
    __shared__ float s_b[KC][Q_ + 4];

    const int tid = threadIdx.x;
    const int tq  = tid & 7;     // 8 q-groups
    const int tn  = tid >> 3;    // 16 n-groups
    const int m   = blockIdx.y;
    const int n0  = blockIdx.x * BN;

    const float* Ab = a + (size_t)n0 * D_;
    const float* Bb = b + (size_t)m * Q_ * D_;

    // acc[i][jp]: i -> 8 n values, jp -> 4 packed q-pairs (8 q values)
    unsigned long long acc[8][4];
    #pragma unroll
    for (int i = 0; i < 8; i++)
        #pragma unroll
        for (int j = 0; j < 4; j++) acc[i][j] = 0ull;

    for (int ks = 0; ks < D_; ks += KC) {
        // ---- stage A tile: 128 rows x KC, transpose into s_a[k][n] ----
        #pragma unroll
        for (int j = 0; j < 8; j++) {
            int e4  = tid + j * NTH;          // float4 index, 1024 total
            int row = e4 >> 3;                // 8 float4 per row
            int c4  = (e4 & 7) << 2;
            float4 v = *reinterpret_cast<const float4*>(Ab + (size_t)row * D_ + ks + c4);
            s_a[c4 + 0][row] = v.x;
            s_a[c4 + 1][row] = v.y;
            s_a[c4 + 2][row] = v.z;
            s_a[c4 + 3][row] = v.w;
        }
        // ---- stage B tile: 64 rows x KC, transpose into s_b[k][q] ----
        #pragma unroll
        for (int j = 0; j < 4; j++) {
            int e4  = tid + j * NTH;
            int row = e4 >> 3;
            int c4  = (e4 & 7) << 2;
            float4 v = *reinterpret_cast<const float4*>(Bb + (size_t)row * D_ + ks + c4);
            s_b[c4 + 0][row] = v.x;
            s_b[c4 + 1][row] = v.y;
            s_b[c4 + 2][row] = v.z;
            s_b[c4 + 3][row] = v.w;
        }
        __syncthreads();

        #pragma unroll 8
        for (int k = 0; k < KC; k++) {
            float4 a0 = *reinterpret_cast<const float4*>(&s_a[k][4 * tn]);
            float4 a1 = *reinterpret_cast<const float4*>(&s_a[k][64 + 4 * tn]);
            F4U b0, b1;
            b0.f4 = *reinterpret_cast<const float4*>(&s_b[k][4 * tq]);
            b1.f4 = *reinterpret_cast<const float4*>(&s_b[k][32 + 4 * tq]);
            unsigned long long bp0 = b0.u[0], bp1 = b0.u[1];
            unsigned long long bp2 = b1.u[0], bp3 = b1.u[1];

            float av[8] = {a0.x, a0.y, a0.z, a0.w, a1.x, a1.y, a1.z, a1.w};
            #pragma unroll
            for (int i = 0; i < 8; i++) {
                unsigned long long ap;
                asm("mov.b64 %0, {%1,%1};" : "=l"(ap) : "f"(av[i]));
                asm("fma.rn.f32x2 %0, %1, %2, %0;" : "+l"(acc[i][0]) : "l"(ap), "l"(bp0));
                asm("fma.rn.f32x2 %0, %1, %2, %0;" : "+l"(acc[i][1]) : "l"(ap), "l"(bp1));
                asm("fma.rn.f32x2 %0, %1, %2, %0;" : "+l"(acc[i][2]) : "l"(ap), "l"(bp2));
                asm("fma.rn.f32x2 %0, %1, %2, %0;" : "+l"(acc[i][3]) : "l"(ap), "l"(bp3));
            }
        }
        __syncthreads();
    }

    // ---- epilogue: exp + Q-reduction ----
    const float iv = 1.0f / var[0];

    // q for (jp, h): (jp<2 ? 0 : 32) + 4*tq + (jp&1)*2 + h
    float cbv[4][2];
    #pragma unroll
    for (int jp = 0; jp < 4; jp++)
        #pragma unroll
        for (int h = 0; h < 2; h++) {
            int q = ((jp < 2) ? 0 : 32) + 4 * tq + ((jp & 1) << 1) + h;
            cbv[jp][h] = g_cb[m * Q_ + q];
        }

    #pragma unroll
    for (int i = 0; i < 8; i++) {
        int n = n0 + ((i < 4) ? (4 * tn + i) : (64 + 4 * tn + (i - 4)));
        float ca_i = g_ca[n];
        float s = 0.0f;
        #pragma unroll
        for (int jp = 0; jp < 4; jp++) {
            UPK x; x.u = acc[i][jp];
            s += __expf(fmaf(x.f[0], iv, ca_i + cbv[jp][0]));
            s += __expf(fmaf(x.f[1], iv, ca_i + cbv[jp][1]));
        }
        // reduce over 8 tq lanes (aligned 8-lane groups within the warp)
        s += __shfl_xor_sync(0xffffffffu, s, 1);
        s += __shfl_xor_sync(0xffffffffu, s, 2);
        s += __shfl_xor_sync(0xffffffffu, s, 4);
        if (tq == 0) dens[(size_t)n * M_ + m] = s;
    }
}

// ---------------------------------------------------------------------------
// Normalize: one warp per n-row, in-place on d_out.
// ---------------------------------------------------------------------------
__global__ __launch_bounds__(256) void kde_norm(float* __restrict__ out) {
    int warp = (blockIdx.x * blockDim.x + threadIdx.x) >> 5;
    int lane = threadIdx.x & 31;
    if (warp >= N_) return;
    float4* row = reinterpret_cast<float4*>(out + (size_t)warp * M_);
    float4 v = row[lane];                       // 32 lanes * 4 = 128 = M
    float s = v.x + v.y + v.z + v.w;
    #pragma unroll
    for (int o = 16; o; o >>= 1) s += __shfl_xor_sync(0xffffffffu, s, o);
    float inv = 1.0f / (s + 1e-10f);
    v.x *= inv; v.y *= inv; v.z *= inv; v.w *= inv;
    row[lane] = v;
}

// ---------------------------------------------------------------------------
extern "C" void kernel_launch(void* const* d_in, const int* in_sizes, int n_in,
                              void* d_out, int out_size) {
    const float* a   = (const float*)d_in[0];   // [4096,128]
    const float* b   = (const float*)d_in[1];   // [128,64,128]
    const float* var = (const float*)d_in[2];   // [1]
    float* out = (float*)d_out;                 // [4096,128]

    // 12288 rows, 8 warps/block
    kde_prep<<<(N_ + M_ * Q_) / 8, 256>>>(a, b, var);

    dim3 grid(N_ / BN, M_);
    kde_main<<<grid, NTH>>>(a, b, var, out);

    kde_norm<<<N_ / 8, 256>>>(out);
}

// round 6
// speedup vs baseline: 2.3062x; 2.3062x over previous
#include <cuda_runtime.h>
#include <cuda_bf16.h>
#include <cstdint>

// Shapes (fixed)
#define N_    4096
#define M_    128
#define Q_    64
#define D_    128
#define MQ_   8192
#define KCAT  384            // [hi | lo | hi] split along K

// ---------------- device scratch (static, allowed) -------------------------
__device__ float g_ca[N_];
__device__ float g_cb[MQ_];
__device__ __nv_bfloat16 g_Acat[(size_t)N_ * KCAT];   // [hiA, loA, hiA]
__device__ __nv_bfloat16 g_Bcat[(size_t)MQ_ * KCAT];  // [hiB, hiB, loB]

#define SWZ(x) ((x) ^ (((x) >> 3) & 0x70))

__device__ __forceinline__ uint32_t smem_u32(const void* p) {
    uint32_t a;
    asm("{ .reg .u64 t; cvta.to.shared.u64 t, %1; cvt.u32.u64 %0, t; }"
        : "=r"(a) : "l"(p));
    return a;
}

#define CP_ASYNC16(dst, src) \
    asm volatile("cp.async.cg.shared.global [%0], [%1], 16;" \
                 :: "r"(dst), "l"(src))
#define CP_COMMIT() asm volatile("cp.async.commit_group;" ::: "memory")

#define LDSM4(r0, r1, r2, r3, addr) \
    asm volatile("ldmatrix.sync.aligned.m8n8.x4.shared.b16 {%0,%1,%2,%3}, [%4];" \
                 : "=r"(r0), "=r"(r1), "=r"(r2), "=r"(r3) : "r"(addr))

#define MMA16816(cc, aa, b0, b1) \
    asm volatile("mma.sync.aligned.m16n8k16.row.col.f32.bf16.bf16.f32 " \
                 "{%0,%1,%2,%3}, {%4,%5,%6,%7}, {%8,%9}, {%0,%1,%2,%3};" \
                 : "+f"((cc)[0]), "+f"((cc)[1]), "+f"((cc)[2]), "+f"((cc)[3]) \
                 : "r"((aa)[0]), "r"((aa)[1]), "r"((aa)[2]), "r"((aa)[3]), \
                   "r"(b0), "r"(b1))

// ---------------- prep: norms + hi/lo bf16 split ---------------------------
__global__ __launch_bounds__(256) void kde_prep(const float* __restrict__ a,
                                                const float* __restrict__ b,
                                                const float* __restrict__ var) {
    int warp = (blockIdx.x * blockDim.x + threadIdx.x) >> 5;
    int lane = threadIdx.x & 31;
    if (warp >= N_ + MQ_) return;
    bool isA = warp < N_;
    const float* src = isA ? (a + (size_t)warp * D_)
                           : (b + (size_t)(warp - N_) * D_);
    float4 v = reinterpret_cast<const float4*>(src)[lane];
    float s = v.x * v.x + v.y * v.y + v.z * v.z + v.w * v.w;
    #pragma unroll
    for (int o = 16; o; o >>= 1) s += __shfl_xor_sync(0xffffffffu, s, o);
    if (lane == 0) {
        float c = -0.5f * (1.0f / var[0]) * s;
        if (isA) g_ca[warp] = c; else g_cb[warp - N_] = c;
    }
    float f[4] = {v.x, v.y, v.z, v.w};
    union { unsigned long long u; __nv_bfloat16 h[4]; } HP, LP;
    #pragma unroll
    for (int i = 0; i < 4; i++) {
        __nv_bfloat16 h = __float2bfloat16(f[i]);
        HP.h[i] = h;
        LP.h[i] = __float2bfloat16(f[i] - __bfloat162float(h));
    }
    __nv_bfloat16* base = isA ? (g_Acat + (size_t)warp * KCAT)
                              : (g_Bcat + (size_t)(warp - N_) * KCAT);
    int off = 4 * lane;
    // A: [hi, lo, hi]   B: [hi, hi, lo]  ->  hi*hi + lo*hi + hi*lo
    *(unsigned long long*)(base + off)       = HP.u;
    *(unsigned long long*)(base + 128 + off) = isA ? LP.u : HP.u;
    *(unsigned long long*)(base + 256 + off) = isA ? HP.u : LP.u;
}

// ---------------- main: warp-MMA GEMM + fused exp/Q-sum --------------------
// CTA tile 128(n) x 128(mq); K = 384 in six 64-elem chunks, double-buffered
// cp.async.  8 warps as 4(m) x 2(n): warp tile 32 x 64.
#define OFF_A0 0
#define OFF_A1 16384
#define OFF_B0 32768
#define OFF_B1 49152
#define OFF_CB 65536
#define SMEM_USE (OFF_CB + 512)
#define SMEM_TOTAL (SMEM_USE + 1024)   // alignment slack

__global__ __launch_bounds__(256, 2) void kde_main(const float* __restrict__ var,
                                                   float* __restrict__ dens) {
    extern __shared__ char smem_raw[];
    uint32_t sb_raw = smem_u32(smem_raw);
    uint32_t sb = (sb_raw + 1023) & ~1023u;
    char* smem = smem_raw + (sb - sb_raw);

    const int tid  = threadIdx.x;
    const int lane = tid & 31;
    const int wid  = tid >> 5;
    const int wm   = wid & 3;     // 4 warps along n-rows
    const int wn   = wid >> 2;    // 2 warps along mq-cols

    if (tid < 128)
        ((float*)(smem + OFF_CB))[tid] = g_cb[blockIdx.y * 128 + tid];

    const __nv_bfloat16* Abase = g_Acat + (size_t)(blockIdx.x * 128) * KCAT;
    const __nv_bfloat16* Bbase = g_Bcat + (size_t)(blockIdx.y * 128) * KCAT;

    float acc[2][8][4];
    #pragma unroll
    for (int t = 0; t < 2; t++)
        #pragma unroll
        for (int nt = 0; nt < 8; nt++)
            #pragma unroll
            for (int r = 0; r < 4; r++) acc[t][nt][r] = 0.0f;

    // ---- stage chunk c into buffer bsel -----------------------------------
    auto stage = [&](int c, int bsel) {
        uint32_t ad = sb + (bsel ? OFF_A1 : OFF_A0);
        uint32_t bd = sb + (bsel ? OFF_B1 : OFF_B0);
        #pragma unroll
        for (int j = 0; j < 4; j++) {                 // A: 1024 x 16B
            int idx = tid + j * 256;
            int row = idx >> 3, col = idx & 7;
            const void* src = Abase + (size_t)row * KCAT + c * 64 + col * 8;
            CP_ASYNC16(ad + SWZ((uint32_t)(row * 128 + col * 16)), src);
        }
        #pragma unroll
        for (int j = 0; j < 4; j++) {                 // B: 1024 x 16B
            int idx = tid + j * 256;
            int row = idx >> 3, col = idx & 7;
            const void* src = Bbase + (size_t)row * KCAT + c * 64 + col * 8;
            CP_ASYNC16(bd + SWZ((uint32_t)(row * 128 + col * 16)), src);
        }
        CP_COMMIT();
    };

    // ---- compute one 64-K chunk from buffer bsel --------------------------
    auto compute = [&](int bsel) {
        uint32_t abase = sb + (bsel ? OFF_A1 : OFF_A0);
        uint32_t bbase = sb + (bsel ? OFF_B1 : OFF_B0);
        #pragma unroll
        for (int ks = 0; ks < 4; ks++) {
            // A fragments: 2 m16xk16 tiles
            uint32_t af[2][4];
            #pragma unroll
            for (int t = 0; t < 2; t++) {
                int row  = wm * 32 + t * 16 + (lane & 7) + ((lane & 8) ? 8 : 0);
                int colb = ks * 32 + ((lane & 16) ? 16 : 0);
                LDSM4(af[t][0], af[t][1], af[t][2], af[t][3],
                      abase + SWZ((uint32_t)(row * 128 + colb)));
            }
            // B fragments: 8 n8xk16 tiles (loaded as 4 x ldmatrix.x4)
            uint32_t bf[8][2];
            #pragma unroll
            for (int p = 0; p < 4; p++) {
                int row  = wn * 64 + p * 16 + (lane & 7) + ((lane & 16) ? 8 : 0);
                int colb = ks * 32 + ((lane & 8) ? 16 : 0);
                LDSM4(bf[2 * p][0], bf[2 * p][1], bf[2 * p + 1][0], bf[2 * p + 1][1],
                      bbase + SWZ((uint32_t)(row * 128 + colb)));
            }
            #pragma unroll
            for (int t = 0; t < 2; t++)
                #pragma unroll
                for (int nt = 0; nt < 8; nt++)
                    MMA16816(acc[t][nt], af[t], bf[nt][0], bf[nt][1]);
        }
    };

    stage(0, 0);
    #pragma unroll
    for (int c = 0; c < 6; c++) {
        int bsel = c & 1;
        if (c + 1 < 6) stage(c + 1, bsel ^ 1);
        if (c + 1 < 6) asm volatile("cp.async.wait_group 1;" ::: "memory");
        else           asm volatile("cp.async.wait_group 0;" ::: "memory");
        __syncthreads();
        compute(bsel);
        __syncthreads();   // buffer safe to overwrite next iteration
    }

    // ---- epilogue: exp + Q-sum (warp's 64 cols == one m-cluster) ----------
    const float iv = 1.0f / var[0];
    const float* cbp = (const float*)(smem + OFF_CB);
    const int mcl = blockIdx.y * 2 + wn;

    #pragma unroll
    for (int t = 0; t < 2; t++) {
        #pragma unroll
        for (int h = 0; h < 2; h++) {
            int row = blockIdx.x * 128 + wm * 32 + t * 16 + h * 8 + (lane >> 2);
            float ca = g_ca[row];
            float s = 0.0f;
            #pragma unroll
            for (int nt = 0; nt < 8; nt++) {
                int ncol = wn * 64 + nt * 8 + (lane & 3) * 2;
                s += __expf(fmaf(acc[t][nt][h * 2 + 0], iv, ca + cbp[ncol]));
                s += __expf(fmaf(acc[t][nt][h * 2 + 1], iv, ca + cbp[ncol + 1]));
            }
            s += __shfl_xor_sync(0xffffffffu, s, 1);
            s += __shfl_xor_sync(0xffffffffu, s, 2);
            if ((lane & 3) == 0) dens[(size_t)row * M_ + mcl] = s;
        }
    }
}

// ---------------- normalize rows -------------------------------------------
__global__ __launch_bounds__(256) void kde_norm(float* __restrict__ out) {
    int warp = (blockIdx.x * blockDim.x + threadIdx.x) >> 5;
    int lane = threadIdx.x & 31;
    if (warp >= N_) return;
    float4* row = reinterpret_cast<float4*>(out + (size_t)warp * M_);
    float4 v = row[lane];
    float s = v.x + v.y + v.z + v.w;
    #pragma unroll
    for (int o = 16; o; o >>= 1) s += __shfl_xor_sync(0xffffffffu, s, o);
    float inv = 1.0f / (s + 1e-10f);
    v.x *= inv; v.y *= inv; v.z *= inv; v.w *= inv;
    row[lane] = v;
}

// ---------------------------------------------------------------------------
extern "C" void kernel_launch(void* const* d_in, const int* in_sizes, int n_in,
                              void* d_out, int out_size) {
    const float* a   = (const float*)d_in[0];   // [4096,128]
    const float* b   = (const float*)d_in[1];   // [128,64,128]
    const float* var = (const float*)d_in[2];   // [1]
    float* out = (float*)d_out;                 // [4096,128]

    cudaFuncSetAttribute(kde_main, cudaFuncAttributeMaxDynamicSharedMemorySize,
                         SMEM_TOTAL);

    kde_prep<<<(N_ + MQ_) / 8, 256>>>(a, b, var);
    kde_main<<<dim3(N_ / 128, MQ_ / 128), 256, SMEM_TOTAL>>>(var, out);
    kde_norm<<<N_ / 8, 256>>>(out);
}

// round 8
// speedup vs baseline: 2.5129x; 1.0897x over previous
#include <cuda_runtime.h>
#include <cuda_bf16.h>
#include <cstdint>

// Shapes (fixed)
#define N_    4096
#define M_    128
#define Q_    64
#define D_    128
#define MQ_   8192
#define KSP   256            // stored split: [hi | lo]
// effective GEMM K = 384 via chunk remap: A {0,1,2,3,0,1}, B {0,1,0,1,2,3}

// ---------------- device scratch (static, allowed) -------------------------
__device__ float g_ca[N_];
__device__ float g_cb[MQ_];
__device__ __nv_bfloat16 g_Acat[(size_t)N_ * KSP];    // [hiA | loA]
__device__ __nv_bfloat16 g_Bcat[(size_t)MQ_ * KSP];   // [hiB | loB]

#define SWZ(x) ((x) ^ (((x) >> 3) & 0x70))

__device__ __forceinline__ uint32_t smem_u32(const void* p) {
    uint32_t a;
    asm("{ .reg .u64 t; cvta.to.shared.u64 t, %1; cvt.u32.u64 %0, t; }"
        : "=r"(a) : "l"(p));
    return a;
}

#define CP_ASYNC16(dst, src) \
    asm volatile("cp.async.cg.shared.global [%0], [%1], 16;" \
                 :: "r"(dst), "l"(src))
#define CP_COMMIT() asm volatile("cp.async.commit_group;" ::: "memory")

#define LDSM4(r0, r1, r2, r3, addr) \
    asm volatile("ldmatrix.sync.aligned.m8n8.x4.shared.b16 {%0,%1,%2,%3}, [%4];" \
                 : "=r"(r0), "=r"(r1), "=r"(r2), "=r"(r3) : "r"(addr))

#define MMA16816(cc, aa, b0, b1) \
    asm volatile("mma.sync.aligned.m16n8k16.row.col.f32.bf16.bf16.f32 " \
                 "{%0,%1,%2,%3}, {%4,%5,%6,%7}, {%8,%9}, {%0,%1,%2,%3};" \
                 : "+f"((cc)[0]), "+f"((cc)[1]), "+f"((cc)[2]), "+f"((cc)[3]) \
                 : "r"((aa)[0]), "r"((aa)[1]), "r"((aa)[2]), "r"((aa)[3]), \
                   "r"(b0), "r"(b1))

// ---------------- prep: norms + hi/lo bf16 split ---------------------------
__global__ __launch_bounds__(256) void kde_prep(const float* __restrict__ a,
                                                const float* __restrict__ b,
                                                const float* __restrict__ var) {
    int warp = (blockIdx.x * blockDim.x + threadIdx.x) >> 5;
    int lane = threadIdx.x & 31;
    if (warp >= N_ + MQ_) return;
    bool isA = warp < N_;
    const float* src = isA ? (a + (size_t)warp * D_)
                           : (b + (size_t)(warp - N_) * D_);
    float4 v = reinterpret_cast<const float4*>(src)[lane];
    float s = v.x * v.x + v.y * v.y + v.z * v.z + v.w * v.w;
    #pragma unroll
    for (int o = 16; o; o >>= 1) s += __shfl_xor_sync(0xffffffffu, s, o);
    if (lane == 0) {
        float c = -0.5f * (1.0f / var[0]) * s;
        if (isA) g_ca[warp] = c; else g_cb[warp - N_] = c;
    }
    float f[4] = {v.x, v.y, v.z, v.w};
    union { unsigned long long u; __nv_bfloat16 h[4]; } HP, LP;
    #pragma unroll
    for (int i = 0; i < 4; i++) {
        __nv_bfloat16 h = __float2bfloat16(f[i]);
        HP.h[i] = h;
        LP.h[i] = __float2bfloat16(f[i] - __bfloat162float(h));
    }
    __nv_bfloat16* base = isA ? (g_Acat + (size_t)warp * KSP)
                              : (g_Bcat + (size_t)(warp - N_) * KSP);
    int off = 4 * lane;
    *(unsigned long long*)(base + off)       = HP.u;   // hi
    *(unsigned long long*)(base + 128 + off) = LP.u;   // lo
}

// ---------------- main: warp-MMA GEMM + fused exp/Q-sum --------------------
// CTA tile 128(n) x 128(mq); effective K=384 as six 64-elem chunks,
// 3-stage cp.async pipeline.  4 warps as 2(m) x 2(n): warp tile 64 x 64.
#define STAGE_BYTES 32768           // A 16KB + B 16KB per stage
#define OFF_B_IN    16384
#define OFF_CB      (3 * STAGE_BYTES)
#define SMEM_USE    (OFF_CB + 512)
#define SMEM_TOTAL  (SMEM_USE + 1024)   // alignment slack

__global__ __launch_bounds__(128, 2) void kde_main(const float* __restrict__ var,
                                                   float* __restrict__ dens) {
    extern __shared__ char smem_raw[];
    uint32_t sb_raw = smem_u32(smem_raw);
    uint32_t sb = (sb_raw + 1023) & ~1023u;
    char* smem = smem_raw + (sb - sb_raw);

    const int tid  = threadIdx.x;
    const int lane = tid & 31;
    const int wid  = tid >> 5;
    const int wm   = wid & 1;     // 2 warps along n-rows (64 each)
    const int wn   = wid >> 1;    // 2 warps along mq-cols (64 each)

    ((float*)(smem + OFF_CB))[tid] = g_cb[blockIdx.y * 128 + tid];

    const __nv_bfloat16* Abase = g_Acat + (size_t)(blockIdx.x * 128) * KSP;
    const __nv_bfloat16* Bbase = g_Bcat + (size_t)(blockIdx.y * 128) * KSP;

    float acc[4][8][4];
    #pragma unroll
    for (int t = 0; t < 4; t++)
        #pragma unroll
        for (int nt = 0; nt < 8; nt++)
            #pragma unroll
            for (int r = 0; r < 4; r++) acc[t][nt][r] = 0.0f;

    // ---- stage chunk c into pipeline buffer s -----------------------------
    auto stage = [&](int c, int s) {
        // chunk -> stored 64-elem chunk index: A {0,1,2,3,0,1}, B {0,1,0,1,2,3}
        int ac = c & 3;
        int bc = (c < 4) ? (c & 1) : (c - 2);
        uint32_t ad = sb + s * STAGE_BYTES;
        uint32_t bd = ad + OFF_B_IN;
        #pragma unroll
        for (int j = 0; j < 8; j++) {                 // A: 1024 x 16B
            int idx = tid + j * 128;
            int row = idx >> 3, col = idx & 7;
            const void* src = Abase + (size_t)row * KSP + ac * 64 + col * 8;
            CP_ASYNC16(ad + SWZ((uint32_t)(row * 128 + col * 16)), src);
        }
        #pragma unroll
        for (int j = 0; j < 8; j++) {                 // B: 1024 x 16B
            int idx = tid + j * 128;
            int row = idx >> 3, col = idx & 7;
            const void* src = Bbase + (size_t)row * KSP + bc * 64 + col * 8;
            CP_ASYNC16(bd + SWZ((uint32_t)(row * 128 + col * 16)), src);
        }
        CP_COMMIT();
    };

    // ---- compute one 64-K chunk from buffer s -----------------------------
    auto compute = [&](int s) {
        uint32_t abase = sb + s * STAGE_BYTES;
        uint32_t bbase = abase + OFF_B_IN;
        #pragma unroll
        for (int ks = 0; ks < 4; ks++) {
            uint32_t af[4][4];
            #pragma unroll
            for (int t = 0; t < 4; t++) {
                int row  = wm * 64 + t * 16 + (lane & 7) + ((lane & 8) ? 8 : 0);
                int colb = ks * 32 + ((lane & 16) ? 16 : 0);
                LDSM4(af[t][0], af[t][1], af[t][2], af[t][3],
                      abase + SWZ((uint32_t)(row * 128 + colb)));
            }
            uint32_t bf[8][2];
            #pragma unroll
            for (int p = 0; p < 4; p++) {
                int row  = wn * 64 + p * 16 + (lane & 7) + ((lane & 16) ? 8 : 0);
                int colb = ks * 32 + ((lane & 8) ? 16 : 0);
                LDSM4(bf[2 * p][0], bf[2 * p][1], bf[2 * p + 1][0], bf[2 * p + 1][1],
                      bbase + SWZ((uint32_t)(row * 128 + colb)));
            }
            #pragma unroll
            for (int t = 0; t < 4; t++)
                #pragma unroll
                for (int nt = 0; nt < 8; nt++)
                    MMA16816(acc[t][nt], af[t], bf[nt][0], bf[nt][1]);
        }
    };

    // ---- 3-stage pipeline over 6 chunks -----------------------------------
    stage(0, 0);
    stage(1, 1);
    #pragma unroll
    for (int c = 0; c < 6; c++) {
        if (c < 5) asm volatile("cp.async.wait_group 1;" ::: "memory");
        else       asm volatile("cp.async.wait_group 0;" ::: "memory");
        __syncthreads();
        if (c + 2 < 6) stage(c + 2, (c + 2) % 3);
        compute(c % 3);
    }

    // ---- epilogue: exp + Q-sum (warp's 64 cols == one m-cluster) ----------
    const float iv = 1.0f / var[0];
    const float* cbp = (const float*)(smem + OFF_CB);
    const int mcl = blockIdx.y * 2 + wn;

    #pragma unroll
    for (int t = 0; t < 4; t++) {
        #pragma unroll
        for (int h = 0; h < 2; h++) {
            int row = blockIdx.x * 128 + wm * 64 + t * 16 + h * 8 + (lane >> 2);
            float ca = g_ca[row];
            float s = 0.0f;
            #pragma unroll
            for (int nt = 0; nt < 8; nt++) {
                int ncol = wn * 64 + nt * 8 + (lane & 3) * 2;
                s += __expf(fmaf(acc[t][nt][h * 2 + 0], iv, ca + cbp[ncol]));
                s += __expf(fmaf(acc[t][nt][h * 2 + 1], iv, ca + cbp[ncol + 1]));
            }
            s += __shfl_xor_sync(0xffffffffu, s, 1);
            s += __shfl_xor_sync(0xffffffffu, s, 2);
            if ((lane & 3) == 0) dens[(size_t)row * M_ + mcl] = s;
        }
    }
}

// ---------------- normalize rows -------------------------------------------
__global__ __launch_bounds__(256) void kde_norm(float* __restrict__ out) {
    int warp = (blockIdx.x * blockDim.x + threadIdx.x) >> 5;
    int lane = threadIdx.x & 31;
    if (warp >= N_) return;
    float4* row = reinterpret_cast<float4*>(out + (size_t)warp * M_);
    float4 v = row[lane];
    float s = v.x + v.y + v.z + v.w;
    #pragma unroll
    for (int o = 16; o; o >>= 1) s += __shfl_xor_sync(0xffffffffu, s, o);
    float inv = 1.0f / (s + 1e-10f);
    v.x *= inv; v.y *= inv; v.z *= inv; v.w *= inv;
    row[lane] = v;
}

// ---------------------------------------------------------------------------
extern "C" void kernel_launch(void* const* d_in, const int* in_sizes, int n_in,
                              void* d_out, int out_size) {
    const float* a   = (const float*)d_in[0];   // [4096,128]
    const float* b   = (const float*)d_in[1];   // [128,64,128]
    const float* var = (const float*)d_in[2];   // [1]
    float* out = (float*)d_out;                 // [4096,128]

    cudaFuncSetAttribute(kde_main, cudaFuncAttributeMaxDynamicSharedMemorySize,
                         SMEM_TOTAL);

    kde_prep<<<(N_ + MQ_) / 8, 256>>>(a, b, var);
    kde_main<<<dim3(N_ / 128, MQ_ / 128), 128, SMEM_TOTAL>>>(var, out);
    kde_norm<<<N_ / 8, 256>>>(out);
}